// round 7
// baseline (speedup 1.0000x reference)
#include <cuda_runtime.h>
#include <cuda_bf16.h>
#include <stdint.h>

#define HID   1024
#define NSEQ  1024
#define DHEAD 64

__device__ float g_q[NSEQ * HID];
__device__ float g_k[NSEQ * HID];
__device__ float g_v[NSEQ * HID];
__device__ float g_pk[2048 * HID];
__device__ float g_pq[2048 * HID];
__device__ __nv_bfloat16 g_scores[16 * NSEQ * NSEQ];  // exp(S) in bf16
__device__ __nv_bfloat16 g_vt[HID * NSEQ];            // V transposed [h*64+d][j]
__device__ float g_psum[16 * NSEQ * 8];
__device__ float g_rinv[16 * NSEQ];
__device__ float g_ctx[NSEQ * HID];
__device__ float g_proj[NSEQ * HID];

__device__ __forceinline__ uint32_t f2bf2(float lo, float hi) {
    uint32_t r;
    asm("cvt.rn.bf16x2.f32 %0, %1, %2;" : "=r"(r) : "f"(hi), "f"(lo));
    return r;
}
__device__ __forceinline__ void mma16(float* c, const uint32_t* a, const uint32_t* b) {
    asm volatile(
        "mma.sync.aligned.m16n8k16.row.col.f32.bf16.bf16.f32 "
        "{%0,%1,%2,%3}, {%4,%5,%6,%7}, {%8,%9}, {%0,%1,%2,%3};\n"
        : "+f"(c[0]), "+f"(c[1]), "+f"(c[2]), "+f"(c[3])
        : "r"(a[0]), "r"(a[1]), "r"(a[2]), "r"(a[3]), "r"(b[0]), "r"(b[1]));
}
__device__ __forceinline__ void ldsm4(uint32_t* r, uint32_t addr) {
    asm volatile("ldmatrix.sync.aligned.m8n8.x4.shared.b16 {%0,%1,%2,%3}, [%4];\n"
        : "=r"(r[0]), "=r"(r[1]), "=r"(r[2]), "=r"(r[3]) : "r"(addr));
}
__device__ __forceinline__ uint32_t smem_u32(const void* p) {
    return (uint32_t)__cvta_generic_to_shared(p);
}

#define ASTRIDE 40

// ============== bf16 NT GEMM (unchanged from R6) ==============
__global__ __launch_bounds__(256)
void gemm_bf16(const float* __restrict__ A,
               const float* __restrict__ W0, const float* __restrict__ b0, float* __restrict__ C0,
               const float* __restrict__ W1, const float* __restrict__ b1, float* __restrict__ C1,
               const float* __restrict__ W2, const float* __restrict__ b2, float* __restrict__ C2)
{
    __shared__ __nv_bfloat16 As[2][128 * ASTRIDE];
    __shared__ __nv_bfloat16 Ws[2][128 * ASTRIDE];

    const int z = blockIdx.z;
    const float* W    = (z == 0) ? W0 : ((z == 1) ? W1 : W2);
    const float* bias = (z == 0) ? b0 : ((z == 1) ? b1 : b2);
    float*       C    = (z == 0) ? C0 : ((z == 1) ? C1 : C2);

    const int m0 = blockIdx.y * 128, n0 = blockIdx.x * 128;
    const int t = threadIdx.x, lane = t & 31, warp = t >> 5;
    const int g = lane >> 2, qd = lane & 3;
    const int wm = warp >> 2, wn = warp & 3;
    const int lr7 = lane & 7;

    const uint32_t aoff = ((uint32_t)((wm * 64 + lr7 + ((lane >> 3) & 1) * 8) * ASTRIDE
                          + (lane >> 4) * 8)) * 2;
    const uint32_t boff = ((uint32_t)((wn * 32 + lr7 + (lane >> 4) * 8) * ASTRIDE
                          + ((lane >> 3) & 1) * 8)) * 2;
    const uint32_t asb = smem_u32(As[0]);
    const uint32_t wsb = smem_u32(Ws[0]);
    const uint32_t bufstep = 128 * ASTRIDE * 2;

    const int lrow = t >> 1, lkoff = (t & 1) * 16;
    const float* Ap = A + (size_t)(m0 + lrow) * HID + lkoff;
    const float* Wp = W + (size_t)(n0 + lrow) * HID + lkoff;

    {
        uint32_t pa[8], pw[8];
#pragma unroll
        for (int f = 0; f < 4; f++) {
            float4 va = *(const float4*)(Ap + f * 4);
            float4 vw = *(const float4*)(Wp + f * 4);
            pa[f*2] = f2bf2(va.x, va.y); pa[f*2+1] = f2bf2(va.z, va.w);
            pw[f*2] = f2bf2(vw.x, vw.y); pw[f*2+1] = f2bf2(vw.z, vw.w);
        }
        uint32_t* da = (uint32_t*)&As[0][lrow * ASTRIDE + lkoff];
        uint32_t* dw = (uint32_t*)&Ws[0][lrow * ASTRIDE + lkoff];
        *(uint4*)da = make_uint4(pa[0], pa[1], pa[2], pa[3]);
        *(uint4*)(da + 4) = make_uint4(pa[4], pa[5], pa[6], pa[7]);
        *(uint4*)dw = make_uint4(pw[0], pw[1], pw[2], pw[3]);
        *(uint4*)(dw + 4) = make_uint4(pw[4], pw[5], pw[6], pw[7]);
    }
    __syncthreads();

    float acc[4][4][4];
#pragma unroll
    for (int i = 0; i < 4; i++)
#pragma unroll
        for (int j = 0; j < 4; j++)
#pragma unroll
            for (int e = 0; e < 4; e++) acc[i][j][e] = 0.0f;

    for (int kt = 0; kt < 32; kt++) {
        const int cur = kt & 1;
        float4 pa4[4], pw4[4];
        const bool more = (kt + 1 < 32);
        if (more) {
#pragma unroll
            for (int f = 0; f < 4; f++) {
                pa4[f] = *(const float4*)(Ap + (kt + 1) * 32 + f * 4);
                pw4[f] = *(const float4*)(Wp + (kt + 1) * 32 + f * 4);
            }
        }
        const uint32_t Abase = asb + cur * bufstep + aoff;
        const uint32_t Bbase = wsb + cur * bufstep + boff;
#pragma unroll
        for (int kk = 0; kk < 2; kk++) {
            uint32_t af[4][4], bf[4][2];
#pragma unroll
            for (int tm = 0; tm < 4; tm++)
                ldsm4(af[tm], Abase + tm * 16 * ASTRIDE * 2 + kk * 32);
#pragma unroll
            for (int tnp = 0; tnp < 2; tnp++) {
                uint32_t bb[4];
                ldsm4(bb, Bbase + tnp * 16 * ASTRIDE * 2 + kk * 32);
                bf[2*tnp][0] = bb[0]; bf[2*tnp][1] = bb[1];
                bf[2*tnp+1][0] = bb[2]; bf[2*tnp+1][1] = bb[3];
            }
#pragma unroll
            for (int tm = 0; tm < 4; tm++)
#pragma unroll
                for (int tn = 0; tn < 4; tn++) mma16(acc[tm][tn], af[tm], bf[tn]);
        }
        if (more) {
            const int nx = cur ^ 1;
            uint32_t qa[8], qw[8];
#pragma unroll
            for (int f = 0; f < 4; f++) {
                qa[f*2] = f2bf2(pa4[f].x, pa4[f].y); qa[f*2+1] = f2bf2(pa4[f].z, pa4[f].w);
                qw[f*2] = f2bf2(pw4[f].x, pw4[f].y); qw[f*2+1] = f2bf2(pw4[f].z, pw4[f].w);
            }
            uint32_t* da = (uint32_t*)&As[nx][lrow * ASTRIDE + lkoff];
            uint32_t* dw = (uint32_t*)&Ws[nx][lrow * ASTRIDE + lkoff];
            *(uint4*)da = make_uint4(qa[0], qa[1], qa[2], qa[3]);
            *(uint4*)(da + 4) = make_uint4(qa[4], qa[5], qa[6], qa[7]);
            *(uint4*)dw = make_uint4(qw[0], qw[1], qw[2], qw[3]);
            *(uint4*)(dw + 4) = make_uint4(qw[4], qw[5], qw[6], qw[7]);
            __syncthreads();
        }
    }

#pragma unroll
    for (int tm = 0; tm < 4; tm++)
#pragma unroll
        for (int tn = 0; tn < 4; tn++) {
            const int row = m0 + wm * 64 + tm * 16 + g;
            const int col = n0 + wn * 32 + tn * 8 + 2 * qd;
            const float bv0 = bias[col], bv1 = bias[col + 1];
            *(float2*)&C[(size_t)row * HID + col] =
                make_float2(acc[tm][tn][0] + bv0, acc[tm][tn][1] + bv1);
            *(float2*)&C[(size_t)(row + 8) * HID + col] =
                make_float2(acc[tm][tn][2] + bv0, acc[tm][tn][3] + bv1);
        }
}

#define QSTRIDE 72

// ===== score: exp scores -> bf16 g_scores, partial row sums -> g_psum =====
__global__ __launch_bounds__(256)
void score_mma()
{
    extern __shared__ char smraw[];
    __nv_bfloat16* qS = (__nv_bfloat16*)smraw;
    __nv_bfloat16* kS = qS + 128 * QSTRIDE;
    __nv_bfloat16* bS = kS + 128 * QSTRIDE;
    float*         Gs = (float*)(bS + 256 * QSTRIDE);

    const int h = blockIdx.z, i0 = blockIdx.y * 128, j0 = blockIdx.x * 128;
    const int t = threadIdx.x, lane = t & 31, warp = t >> 5;
    const int g = lane >> 2, qd = lane & 3;
    const int wm = warp >> 2, wn = warp & 3;
    const int lr7 = lane & 7;

    const uint32_t aoffQ = ((uint32_t)((wm * 64 + lr7 + ((lane >> 3) & 1) * 8) * QSTRIDE
                           + (lane >> 4) * 8)) * 2;
    const uint32_t boffQ = ((uint32_t)((wn * 32 + lr7 + (lane >> 4) * 8) * QSTRIDE
                           + ((lane >> 3) & 1) * 8)) * 2;
    const uint32_t qSb = smem_u32(qS), kSb = smem_u32(kS), bSb = smem_u32(bS);

    {
        const int lrow = t >> 1, dh = (t & 1) * 32;
        const float* qp = g_q + (size_t)(i0 + lrow) * HID + h * DHEAD + dh;
        const float* kp = g_k + (size_t)(j0 + lrow) * HID + h * DHEAD + dh;
        uint32_t uq[16], uk[16];
#pragma unroll
        for (int f = 0; f < 8; f++) {
            float4 a = *(const float4*)(qp + f * 4);
            float4 b = *(const float4*)(kp + f * 4);
            uq[f*2] = f2bf2(a.x, a.y); uq[f*2+1] = f2bf2(a.z, a.w);
            uk[f*2] = f2bf2(b.x, b.y); uk[f*2+1] = f2bf2(b.z, b.w);
        }
        uint32_t* dq = (uint32_t*)&qS[lrow * QSTRIDE + dh];
        uint32_t* dk = (uint32_t*)&kS[lrow * QSTRIDE + dh];
#pragma unroll
        for (int f = 0; f < 4; f++) {
            *(uint4*)(dq + f * 4) = make_uint4(uq[f*4], uq[f*4+1], uq[f*4+2], uq[f*4+3]);
            *(uint4*)(dk + f * 4) = make_uint4(uk[f*4], uk[f*4+1], uk[f*4+2], uk[f*4+3]);
        }
    }
    const int dmin = 1024 + i0 - j0 - 127;
    {
        const int brow = (t < 255) ? t : 254;
        const float* bp = g_pk + (size_t)(dmin + brow) * HID + h * DHEAD;
        uint32_t ub[32];
#pragma unroll
        for (int f = 0; f < 16; f++) {
            float4 a = *(const float4*)(bp + f * 4);
            ub[f*2] = f2bf2(a.x, a.y); ub[f*2+1] = f2bf2(a.z, a.w);
        }
        uint32_t* db = (uint32_t*)&bS[t * QSTRIDE];
#pragma unroll
        for (int f = 0; f < 8; f++)
            *(uint4*)(db + f * 4) = make_uint4(ub[f*4], ub[f*4+1], ub[f*4+2], ub[f*4+3]);
    }
    __syncthreads();

    float S[4][4][4];
#pragma unroll
    for (int i = 0; i < 4; i++)
#pragma unroll
        for (int j = 0; j < 4; j++)
#pragma unroll
            for (int e = 0; e < 4; e++) S[i][j][e] = 0.0f;

#pragma unroll
    for (int kk = 0; kk < 4; kk++) {
        uint32_t af[4][4], bf[4][2];
#pragma unroll
        for (int tm = 0; tm < 4; tm++)
            ldsm4(af[tm], qSb + aoffQ + tm * 16 * QSTRIDE * 2 + kk * 32);
#pragma unroll
        for (int tnp = 0; tnp < 2; tnp++) {
            uint32_t bb[4];
            ldsm4(bb, kSb + boffQ + tnp * 16 * QSTRIDE * 2 + kk * 32);
            bf[2*tnp][0] = bb[0]; bf[2*tnp][1] = bb[1];
            bf[2*tnp+1][0] = bb[2]; bf[2*tnp+1][1] = bb[3];
        }
#pragma unroll
        for (int tm = 0; tm < 4; tm++)
#pragma unroll
            for (int tn = 0; tn < 4; tn++) mma16(S[tm][tn], af[tm], bf[tn]);
    }

    for (int pass = 0; pass < 2; pass++) {
        if (pass == 1) {
            const int brow = (t < 255) ? t : 254;
            const float* bp = g_pq + (size_t)(dmin + brow) * HID + h * DHEAD;
            uint32_t ub[32];
#pragma unroll
            for (int f = 0; f < 16; f++) {
                float4 a = *(const float4*)(bp + f * 4);
                ub[f*2] = f2bf2(a.x, a.y); ub[f*2+1] = f2bf2(a.z, a.w);
            }
            uint32_t* db = (uint32_t*)&bS[t * QSTRIDE];
#pragma unroll
            for (int f = 0; f < 8; f++)
                *(uint4*)(db + f * 4) = make_uint4(ub[f*4], ub[f*4+1], ub[f*4+2], ub[f*4+3]);
            __syncthreads();
        }
        const uint32_t Xb = (pass == 0) ? qSb : kSb;
        for (int bh = 0; bh < 2; bh++) {
            float Ga[4][4][4];
#pragma unroll
            for (int i = 0; i < 4; i++)
#pragma unroll
                for (int j = 0; j < 4; j++)
#pragma unroll
                    for (int e = 0; e < 4; e++) Ga[i][j][e] = 0.0f;
#pragma unroll
            for (int kk = 0; kk < 4; kk++) {
                uint32_t af[4][4], bf[4][2];
#pragma unroll
                for (int tm = 0; tm < 4; tm++)
                    ldsm4(af[tm], Xb + aoffQ + tm * 16 * QSTRIDE * 2 + kk * 32);
#pragma unroll
                for (int tnp = 0; tnp < 2; tnp++) {
                    uint32_t bb[4];
                    ldsm4(bb, bSb + boffQ + (bh * 128 + tnp * 16) * QSTRIDE * 2 + kk * 32);
                    bf[2*tnp][0] = bb[0]; bf[2*tnp][1] = bb[1];
                    bf[2*tnp+1][0] = bb[2]; bf[2*tnp+1][1] = bb[3];
                }
#pragma unroll
                for (int tm = 0; tm < 4; tm++)
#pragma unroll
                    for (int tn = 0; tn < 4; tn++) mma16(Ga[tm][tn], af[tm], bf[tn]);
            }
#pragma unroll
            for (int tm = 0; tm < 4; tm++)
#pragma unroll
                for (int tn = 0; tn < 4; tn++) {
                    const int r = wm * 64 + tm * 16 + g;
                    const int c = wn * 32 + tn * 8 + 2 * qd;
                    *(float2*)&Gs[r * 132 + c] = make_float2(Ga[tm][tn][0], Ga[tm][tn][1]);
                    *(float2*)&Gs[(r + 8) * 132 + c] = make_float2(Ga[tm][tn][2], Ga[tm][tn][3]);
                }
            __syncthreads();
#pragma unroll
            for (int tm = 0; tm < 4; tm++)
#pragma unroll
                for (int tn = 0; tn < 4; tn++) {
                    const int il = wm * 64 + tm * 16 + g;
                    const int jl = wn * 32 + tn * 8 + 2 * qd;
                    const int b0v = il - jl + 127 - bh * 128;
                    const int bv[4] = {b0v, b0v - 1, b0v + 8, b0v + 7};
                    int rv[4];
                    if (pass == 0) { rv[0] = il; rv[1] = il; rv[2] = il + 8; rv[3] = il + 8; }
                    else           { rv[0] = jl; rv[1] = jl + 1; rv[2] = jl; rv[3] = jl + 1; }
#pragma unroll
                    for (int e = 0; e < 4; e++)
                        if ((unsigned)bv[e] < 128u)
                            S[tm][tn][e] += Gs[rv[e] * 132 + bv[e]];
                }
            __syncthreads();
        }
    }

    // epilogue: exp -> bf16 store + partial row sums
    const float inv = 0.07216878364870322992f;
    float rs[4][2];
#pragma unroll
    for (int tm = 0; tm < 4; tm++) {
        float s0 = 0.0f, s1 = 0.0f;
        const int row = i0 + wm * 64 + tm * 16 + g;
        const int colb = j0 + wn * 32 + 2 * qd;
#pragma unroll
        for (int tn = 0; tn < 4; tn++) {
            float e0 = __expf(S[tm][tn][0] * inv);
            float e1 = __expf(S[tm][tn][1] * inv);
            float e2 = __expf(S[tm][tn][2] * inv);
            float e3 = __expf(S[tm][tn][3] * inv);
            s0 += e0 + e1; s1 += e2 + e3;
            *(uint32_t*)&g_scores[((size_t)h * NSEQ + row) * NSEQ + colb + tn * 8] = f2bf2(e0, e1);
            *(uint32_t*)&g_scores[((size_t)h * NSEQ + row + 8) * NSEQ + colb + tn * 8] = f2bf2(e2, e3);
        }
        rs[tm][0] = s0; rs[tm][1] = s1;
    }
#pragma unroll
    for (int tm = 0; tm < 4; tm++) {
        float s0 = rs[tm][0], s1 = rs[tm][1];
        s0 += __shfl_xor_sync(0xffffffffu, s0, 1);
        s0 += __shfl_xor_sync(0xffffffffu, s0, 2);
        s1 += __shfl_xor_sync(0xffffffffu, s1, 1);
        s1 += __shfl_xor_sync(0xffffffffu, s1, 2);
        if (qd == 0) {
            const int r = wm * 64 + tm * 16 + g;
            Gs[r * 4 + wn] = s0;
            Gs[(r + 8) * 4 + wn] = s1;
        }
    }
    __syncthreads();
    if (t < 128) {
        float tot = Gs[t * 4] + Gs[t * 4 + 1] + Gs[t * 4 + 2] + Gs[t * 4 + 3];
        g_psum[((size_t)(h << 10) + i0 + t) * 8 + blockIdx.x] = tot;
    }
}

// ============== rinv: 1/rowsum ==============
__global__ __launch_bounds__(256)
void rinv_kernel()
{
    const int i = blockIdx.x * 256 + threadIdx.x;  // 0..16383
    const float* pp = g_psum + (size_t)i * 8;
    float4 a = *(const float4*)pp, b = *(const float4*)(pp + 4);
    g_rinv[i] = 1.0f / (a.x + a.y + a.z + a.w + b.x + b.y + b.z + b.w);
}

// ============== vt: transpose V to bf16 [c][i] ==============
__global__ __launch_bounds__(256)
void vt_kernel()
{
    __shared__ float tile[32][33];
    const int bx = blockIdx.x;  // c-tile
    const int by = blockIdx.y;  // i-tile
    const int tx = threadIdx.x & 31, ty = threadIdx.x >> 5;
#pragma unroll
    for (int r = 0; r < 4; r++)
        tile[ty + r * 8][tx] = g_v[(size_t)(by * 32 + ty + r * 8) * HID + bx * 32 + tx];
    __syncthreads();
#pragma unroll
    for (int r = 0; r < 4; r++)
        g_vt[(size_t)(bx * 32 + ty + r * 8) * NSEQ + by * 32 + tx] =
            __float2bfloat16(tile[tx][ty + r * 8]);
}

#define PSTR 72

// ============== AV v2: i-tile 64, BJ=64, double-buffered =====================
__global__ __launch_bounds__(256)
void av_mma()
{
    __shared__ __nv_bfloat16 Ps[2][64 * PSTR];
    __shared__ __nv_bfloat16 Vt[2][64 * PSTR];
    const int h = blockIdx.y, i0 = blockIdx.x * 64;
    const int t = threadIdx.x, lane = t & 31, warp = t >> 5;
    const int g = lane >> 2, qd = lane & 3;
    const int wm = warp >> 2, wn = warp & 3;  // wm 0..1, wn 0..3
    const int lr7 = lane & 7;

    const uint32_t aoffP = ((uint32_t)((wm * 32 + lr7 + ((lane >> 3) & 1) * 8) * PSTR
                           + (lane >> 4) * 8)) * 2;
    const uint32_t boffV = ((uint32_t)((wn * 16 + lr7 + (lane >> 4) * 8) * PSTR
                           + ((lane >> 3) & 1) * 8)) * 2;
    const uint32_t PsB = smem_u32(Ps[0]), VtB = smem_u32(Vt[0]);
    const uint32_t bufstep = 64 * PSTR * 2;

    const int srow = t >> 2;           // 0..63
    const int scol = (t & 3) * 16;     // bf16 col within 64-wide tile
    const __nv_bfloat16* sp0 = g_scores + ((size_t)h * NSEQ + i0 + srow) * NSEQ + scol;
    const __nv_bfloat16* vp0 = g_vt + ((size_t)(h * DHEAD) + srow) * NSEQ + scol;
    __nv_bfloat16* pdst = &Ps[0][srow * PSTR + scol];
    __nv_bfloat16* vdst = &Vt[0][srow * PSTR + scol];
    const int sstep = 64 * PSTR;

    // per-row rinv
    float rv[2][2];
#pragma unroll
    for (int tm = 0; tm < 2; tm++) {
        const int rl = wm * 32 + tm * 16 + g;
        rv[tm][0] = g_rinv[h * NSEQ + i0 + rl];
        rv[tm][1] = g_rinv[h * NSEQ + i0 + rl + 8];
    }

    // preload tile 0
    {
        uint4 p0 = *(const uint4*)sp0;
        uint4 p1 = *(const uint4*)(sp0 + 8);
        uint4 v0 = *(const uint4*)vp0;
        uint4 v1 = *(const uint4*)(vp0 + 8);
        *(uint4*)pdst = p0; *(uint4*)(pdst + 8) = p1;
        *(uint4*)vdst = v0; *(uint4*)(vdst + 8) = v1;
    }
    __syncthreads();

    float acc[2][2][4];
#pragma unroll
    for (int i = 0; i < 2; i++)
#pragma unroll
        for (int j = 0; j < 2; j++)
#pragma unroll
            for (int e = 0; e < 4; e++) acc[i][j][e] = 0.0f;

    for (int jt = 0; jt < NSEQ; jt += 64) {
        const int cur = (jt >> 6) & 1;
        const bool more = (jt + 64 < NSEQ);
        uint4 p0, p1, v0, v1;
        if (more) {
            p0 = *(const uint4*)(sp0 + jt + 64);
            p1 = *(const uint4*)(sp0 + jt + 64 + 8);
            v0 = *(const uint4*)(vp0 + jt + 64);
            v1 = *(const uint4*)(vp0 + jt + 64 + 8);
        }
#pragma unroll
        for (int kk = 0; kk < 4; kk++) {
            uint32_t af[2][4], bf[2][2];
#pragma unroll
            for (int tm = 0; tm < 2; tm++)
                ldsm4(af[tm], PsB + cur * bufstep + aoffP + tm * 16 * PSTR * 2 + kk * 32);
            {
                uint32_t bb[4];
                ldsm4(bb, VtB + cur * bufstep + boffV + kk * 32);
                bf[0][0] = bb[0]; bf[0][1] = bb[1];
                bf[1][0] = bb[2]; bf[1][1] = bb[3];
            }
#pragma unroll
            for (int tm = 0; tm < 2; tm++)
#pragma unroll
                for (int tn = 0; tn < 2; tn++) mma16(acc[tm][tn], af[tm], bf[tn]);
        }
        if (more) {
            const int nx = cur ^ 1;
            *(uint4*)(pdst + nx * sstep) = p0; *(uint4*)(pdst + nx * sstep + 8) = p1;
            *(uint4*)(vdst + nx * sstep) = v0; *(uint4*)(vdst + nx * sstep + 8) = v1;
            __syncthreads();
        }
    }

#pragma unroll
    for (int tm = 0; tm < 2; tm++)
#pragma unroll
        for (int tn = 0; tn < 2; tn++) {
            const int row = i0 + wm * 32 + tm * 16 + g;
            const int col = h * DHEAD + wn * 16 + tn * 8 + 2 * qd;
            *(float2*)&g_ctx[(size_t)row * HID + col] =
                make_float2(acc[tm][tn][0] * rv[tm][0], acc[tm][tn][1] * rv[tm][0]);
            *(float2*)&g_ctx[(size_t)(row + 8) * HID + col] =
                make_float2(acc[tm][tn][2] * rv[tm][1], acc[tm][tn][3] * rv[tm][1]);
        }
}

// ============== residual + LayerNorm =========================================
__global__ __launch_bounds__(256)
void ln_kernel(const float* __restrict__ hs, const float* __restrict__ gg,
               const float* __restrict__ bb, float* __restrict__ out)
{
    const int row = blockIdx.x, t = threadIdx.x;
    __shared__ float red[8];
    float4 p = *(const float4*)(g_proj + (size_t)row * HID + t * 4);
    float4 hv = *(const float4*)(hs + (size_t)row * HID + t * 4);
    float x0 = p.x+hv.x, x1 = p.y+hv.y, x2 = p.z+hv.z, x3 = p.w+hv.w;
    float s = x0+x1+x2+x3;
#pragma unroll
    for (int o = 16; o > 0; o >>= 1) s += __shfl_xor_sync(0xffffffffu, s, o);
    if ((t & 31) == 0) red[t >> 5] = s;
    __syncthreads();
    float mu = (red[0]+red[1]+red[2]+red[3]+red[4]+red[5]+red[6]+red[7]) * (1.0f/1024.0f);
    float d0 = x0-mu, d1 = x1-mu, d2 = x2-mu, d3 = x3-mu;
    float sq = d0*d0 + d1*d1 + d2*d2 + d3*d3;
#pragma unroll
    for (int o = 16; o > 0; o >>= 1) sq += __shfl_xor_sync(0xffffffffu, sq, o);
    __syncthreads();
    if ((t & 31) == 0) red[t >> 5] = sq;
    __syncthreads();
    float var = (red[0]+red[1]+red[2]+red[3]+red[4]+red[5]+red[6]+red[7]) * (1.0f/1024.0f);
    float rstd = rsqrtf(var + 1e-7f);
    float4 g4 = *(const float4*)(gg + t * 4);
    float4 b4 = *(const float4*)(bb + t * 4);
    *(float4*)(out + (size_t)row * HID + t * 4) =
        make_float4(d0*rstd*g4.x + b4.x, d1*rstd*g4.y + b4.y,
                    d2*rstd*g4.z + b4.z, d3*rstd*g4.w + b4.w);
}

extern "C" void kernel_launch(void* const* d_in, const int* in_sizes, int n_in,
                              void* d_out, int out_size)
{
    const float* hs  = (const float*)d_in[0];
    const float* rel = (const float*)d_in[1];
    const float* Wq  = (const float*)d_in[2];  const float* bq  = (const float*)d_in[3];
    const float* Wk  = (const float*)d_in[4];  const float* bk  = (const float*)d_in[5];
    const float* Wv  = (const float*)d_in[6];  const float* bv  = (const float*)d_in[7];
    const float* Wpk = (const float*)d_in[8];  const float* bpk = (const float*)d_in[9];
    const float* Wpq = (const float*)d_in[10]; const float* bpq = (const float*)d_in[11];
    const float* Wo  = (const float*)d_in[12]; const float* bo  = (const float*)d_in[13];
    const float* lng = (const float*)d_in[14]; const float* lnb = (const float*)d_in[15];

    float *q_, *k_, *v_, *pk_, *pq_, *ctx_, *proj_;
    cudaGetSymbolAddress((void**)&q_, g_q);
    cudaGetSymbolAddress((void**)&k_, g_k);
    cudaGetSymbolAddress((void**)&v_, g_v);
    cudaGetSymbolAddress((void**)&pk_, g_pk);
    cudaGetSymbolAddress((void**)&pq_, g_pq);
    cudaGetSymbolAddress((void**)&ctx_, g_ctx);
    cudaGetSymbolAddress((void**)&proj_, g_proj);

    const int score_smem = (2 * 128 * QSTRIDE + 256 * QSTRIDE) * 2 + 128 * 132 * 4;
    cudaFuncSetAttribute(score_mma, cudaFuncAttributeMaxDynamicSharedMemorySize, score_smem);

    gemm_bf16<<<dim3(8, 8, 3), 256>>>(hs, Wq, bq, q_, Wk, bk, k_, Wv, bv, v_);
    gemm_bf16<<<dim3(8, 16, 2), 256>>>(rel, Wpk, bpk, pk_, Wpq, bpq, pq_, Wpq, bpq, pq_);
    vt_kernel<<<dim3(32, 32), 256>>>();
    score_mma<<<dim3(8, 8, 16), 256, score_smem>>>();
    rinv_kernel<<<64, 256>>>();
    av_mma<<<dim3(16, 16), 256>>>();
    gemm_bf16<<<dim3(8, 8, 1), 256>>>(ctx_, Wo, bo, proj_, Wo, bo, proj_, Wo, bo, proj_);
    ln_kernel<<<1024, 256>>>(hs, lng, lnb, (float*)d_out);
}

// round 9
// speedup vs baseline: 1.4731x; 1.4731x over previous
#include <cuda_runtime.h>
#include <cuda_bf16.h>
#include <stdint.h>

#define HID   1024
#define NSEQ  1024
#define DHEAD 64

__device__ float g_q[NSEQ * HID];
__device__ float g_k[NSEQ * HID];
__device__ float g_v[NSEQ * HID];
__device__ float g_pk[2048 * HID];
__device__ float g_pq[2048 * HID];
__device__ __nv_bfloat16 g_scores[16 * NSEQ * NSEQ];  // exp(S) in bf16
__device__ float g_psum[16 * NSEQ * 8];
__device__ float g_rinv[16 * NSEQ];
__device__ float g_ctx[NSEQ * HID];
__device__ float g_proj[NSEQ * HID];

__device__ __forceinline__ uint32_t f2bf2(float lo, float hi) {
    uint32_t r;
    asm("cvt.rn.bf16x2.f32 %0, %1, %2;" : "=r"(r) : "f"(hi), "f"(lo));
    return r;
}
__device__ __forceinline__ void mma16(float* c, const uint32_t* a, const uint32_t* b) {
    asm volatile(
        "mma.sync.aligned.m16n8k16.row.col.f32.bf16.bf16.f32 "
        "{%0,%1,%2,%3}, {%4,%5,%6,%7}, {%8,%9}, {%0,%1,%2,%3};\n"
        : "+f"(c[0]), "+f"(c[1]), "+f"(c[2]), "+f"(c[3])
        : "r"(a[0]), "r"(a[1]), "r"(a[2]), "r"(a[3]), "r"(b[0]), "r"(b[1]));
}
__device__ __forceinline__ void ldsm4(uint32_t* r, uint32_t addr) {
    asm volatile("ldmatrix.sync.aligned.m8n8.x4.shared.b16 {%0,%1,%2,%3}, [%4];\n"
        : "=r"(r[0]), "=r"(r[1]), "=r"(r[2]), "=r"(r[3]) : "r"(addr));
}
__device__ __forceinline__ uint32_t smem_u32(const void* p) {
    return (uint32_t)__cvta_generic_to_shared(p);
}

#define ASTRIDE 40

// ============== bf16 NT GEMM (unchanged, proven) ==============
__global__ __launch_bounds__(256)
void gemm_bf16(const float* __restrict__ A,
               const float* __restrict__ W0, const float* __restrict__ b0, float* __restrict__ C0,
               const float* __restrict__ W1, const float* __restrict__ b1, float* __restrict__ C1,
               const float* __restrict__ W2, const float* __restrict__ b2, float* __restrict__ C2)
{
    __shared__ __nv_bfloat16 As[2][128 * ASTRIDE];
    __shared__ __nv_bfloat16 Ws[2][128 * ASTRIDE];

    const int z = blockIdx.z;
    const float* W    = (z == 0) ? W0 : ((z == 1) ? W1 : W2);
    const float* bias = (z == 0) ? b0 : ((z == 1) ? b1 : b2);
    float*       C    = (z == 0) ? C0 : ((z == 1) ? C1 : C2);

    const int m0 = blockIdx.y * 128, n0 = blockIdx.x * 128;
    const int t = threadIdx.x, lane = t & 31, warp = t >> 5;
    const int g = lane >> 2, qd = lane & 3;
    const int wm = warp >> 2, wn = warp & 3;
    const int lr7 = lane & 7;

    const uint32_t aoff = ((uint32_t)((wm * 64 + lr7 + ((lane >> 3) & 1) * 8) * ASTRIDE
                          + (lane >> 4) * 8)) * 2;
    const uint32_t boff = ((uint32_t)((wn * 32 + lr7 + (lane >> 4) * 8) * ASTRIDE
                          + ((lane >> 3) & 1) * 8)) * 2;
    const uint32_t asb = smem_u32(As[0]);
    const uint32_t wsb = smem_u32(Ws[0]);
    const uint32_t bufstep = 128 * ASTRIDE * 2;

    const int lrow = t >> 1, lkoff = (t & 1) * 16;
    const float* Ap = A + (size_t)(m0 + lrow) * HID + lkoff;
    const float* Wp = W + (size_t)(n0 + lrow) * HID + lkoff;

    {
        uint32_t pa[8], pw[8];
#pragma unroll
        for (int f = 0; f < 4; f++) {
            float4 va = *(const float4*)(Ap + f * 4);
            float4 vw = *(const float4*)(Wp + f * 4);
            pa[f*2] = f2bf2(va.x, va.y); pa[f*2+1] = f2bf2(va.z, va.w);
            pw[f*2] = f2bf2(vw.x, vw.y); pw[f*2+1] = f2bf2(vw.z, vw.w);
        }
        uint32_t* da = (uint32_t*)&As[0][lrow * ASTRIDE + lkoff];
        uint32_t* dw = (uint32_t*)&Ws[0][lrow * ASTRIDE + lkoff];
        *(uint4*)da = make_uint4(pa[0], pa[1], pa[2], pa[3]);
        *(uint4*)(da + 4) = make_uint4(pa[4], pa[5], pa[6], pa[7]);
        *(uint4*)dw = make_uint4(pw[0], pw[1], pw[2], pw[3]);
        *(uint4*)(dw + 4) = make_uint4(pw[4], pw[5], pw[6], pw[7]);
    }
    __syncthreads();

    float acc[4][4][4];
#pragma unroll
    for (int i = 0; i < 4; i++)
#pragma unroll
        for (int j = 0; j < 4; j++)
#pragma unroll
            for (int e = 0; e < 4; e++) acc[i][j][e] = 0.0f;

    for (int kt = 0; kt < 32; kt++) {
        const int cur = kt & 1;
        float4 pa4[4], pw4[4];
        const bool more = (kt + 1 < 32);
        if (more) {
#pragma unroll
            for (int f = 0; f < 4; f++) {
                pa4[f] = *(const float4*)(Ap + (kt + 1) * 32 + f * 4);
                pw4[f] = *(const float4*)(Wp + (kt + 1) * 32 + f * 4);
            }
        }
        const uint32_t Abase = asb + cur * bufstep + aoff;
        const uint32_t Bbase = wsb + cur * bufstep + boff;
#pragma unroll
        for (int kk = 0; kk < 2; kk++) {
            uint32_t af[4][4], bf[4][2];
#pragma unroll
            for (int tm = 0; tm < 4; tm++)
                ldsm4(af[tm], Abase + tm * 16 * ASTRIDE * 2 + kk * 32);
#pragma unroll
            for (int tnp = 0; tnp < 2; tnp++) {
                uint32_t bb[4];
                ldsm4(bb, Bbase + tnp * 16 * ASTRIDE * 2 + kk * 32);
                bf[2*tnp][0] = bb[0]; bf[2*tnp][1] = bb[1];
                bf[2*tnp+1][0] = bb[2]; bf[2*tnp+1][1] = bb[3];
            }
#pragma unroll
            for (int tm = 0; tm < 4; tm++)
#pragma unroll
                for (int tn = 0; tn < 4; tn++) mma16(acc[tm][tn], af[tm], bf[tn]);
        }
        if (more) {
            const int nx = cur ^ 1;
            uint32_t qa[8], qw[8];
#pragma unroll
            for (int f = 0; f < 4; f++) {
                qa[f*2] = f2bf2(pa4[f].x, pa4[f].y); qa[f*2+1] = f2bf2(pa4[f].z, pa4[f].w);
                qw[f*2] = f2bf2(pw4[f].x, pw4[f].y); qw[f*2+1] = f2bf2(pw4[f].z, pw4[f].w);
            }
            uint32_t* da = (uint32_t*)&As[nx][lrow * ASTRIDE + lkoff];
            uint32_t* dw = (uint32_t*)&Ws[nx][lrow * ASTRIDE + lkoff];
            *(uint4*)da = make_uint4(qa[0], qa[1], qa[2], qa[3]);
            *(uint4*)(da + 4) = make_uint4(qa[4], qa[5], qa[6], qa[7]);
            *(uint4*)dw = make_uint4(qw[0], qw[1], qw[2], qw[3]);
            *(uint4*)(dw + 4) = make_uint4(qw[4], qw[5], qw[6], qw[7]);
            __syncthreads();
        }
    }

#pragma unroll
    for (int tm = 0; tm < 4; tm++)
#pragma unroll
        for (int tn = 0; tn < 4; tn++) {
            const int row = m0 + wm * 64 + tm * 16 + g;
            const int col = n0 + wn * 32 + tn * 8 + 2 * qd;
            const float bv0 = bias[col], bv1 = bias[col + 1];
            *(float2*)&C[(size_t)row * HID + col] =
                make_float2(acc[tm][tn][0] + bv0, acc[tm][tn][1] + bv1);
            *(float2*)&C[(size_t)(row + 8) * HID + col] =
                make_float2(acc[tm][tn][2] + bv0, acc[tm][tn][3] + bv1);
        }
}

#define QSTRIDE 72

// ===== score (512 threads, 16 warps, warp tile 32x32) =====
__global__ __launch_bounds__(512)
void score_mma()
{
    extern __shared__ char smraw[];
    __nv_bfloat16* qS = (__nv_bfloat16*)smraw;
    __nv_bfloat16* kS = qS + 128 * QSTRIDE;
    __nv_bfloat16* bS = kS + 128 * QSTRIDE;
    float*         Gs = (float*)(bS + 256 * QSTRIDE);

    const int h = blockIdx.z, i0 = blockIdx.y * 128, j0 = blockIdx.x * 128;
    const int t = threadIdx.x, lane = t & 31, warp = t >> 5;
    const int g = lane >> 2, qd = lane & 3;
    const int wm = warp >> 2, wn = warp & 3;   // 4x4 warp grid
    const int lr7 = lane & 7;

    const uint32_t aoffQ = ((uint32_t)((wm * 32 + lr7 + ((lane >> 3) & 1) * 8) * QSTRIDE
                           + (lane >> 4) * 8)) * 2;
    const uint32_t boffQ = ((uint32_t)((wn * 32 + lr7 + (lane >> 4) * 8) * QSTRIDE
                           + ((lane >> 3) & 1) * 8)) * 2;
    const uint32_t qSb = smem_u32(qS), kSb = smem_u32(kS), bSb = smem_u32(bS);

    // stage q, k: 512 thr, 16 floats each
    {
        const int lrow = t >> 2, dh = (t & 3) * 16;
        const float* qp = g_q + (size_t)(i0 + lrow) * HID + h * DHEAD + dh;
        const float* kp = g_k + (size_t)(j0 + lrow) * HID + h * DHEAD + dh;
        uint32_t uq[8], uk[8];
#pragma unroll
        for (int f = 0; f < 4; f++) {
            float4 a = *(const float4*)(qp + f * 4);
            float4 b = *(const float4*)(kp + f * 4);
            uq[f*2] = f2bf2(a.x, a.y); uq[f*2+1] = f2bf2(a.z, a.w);
            uk[f*2] = f2bf2(b.x, b.y); uk[f*2+1] = f2bf2(b.z, b.w);
        }
        uint32_t* dq = (uint32_t*)&qS[lrow * QSTRIDE + dh];
        uint32_t* dk = (uint32_t*)&kS[lrow * QSTRIDE + dh];
        *(uint4*)dq = make_uint4(uq[0], uq[1], uq[2], uq[3]);
        *(uint4*)(dq + 4) = make_uint4(uq[4], uq[5], uq[6], uq[7]);
        *(uint4*)dk = make_uint4(uk[0], uk[1], uk[2], uk[3]);
        *(uint4*)(dk + 4) = make_uint4(uk[4], uk[5], uk[6], uk[7]);
    }
    const int dmin = 1024 + i0 - j0 - 127;
    const int brow = ((t >> 1) < 255) ? (t >> 1) : 254;
    const int bdh  = (t & 1) * 32;
    {
        const float* bp = g_pk + (size_t)(dmin + brow) * HID + h * DHEAD + bdh;
        uint32_t ub[16];
#pragma unroll
        for (int f = 0; f < 8; f++) {
            float4 a = *(const float4*)(bp + f * 4);
            ub[f*2] = f2bf2(a.x, a.y); ub[f*2+1] = f2bf2(a.z, a.w);
        }
        uint32_t* db = (uint32_t*)&bS[brow * QSTRIDE + bdh];
#pragma unroll
        for (int f = 0; f < 4; f++)
            *(uint4*)(db + f * 4) = make_uint4(ub[f*4], ub[f*4+1], ub[f*4+2], ub[f*4+3]);
    }
    __syncthreads();

    float S[2][4][4];
#pragma unroll
    for (int i = 0; i < 2; i++)
#pragma unroll
        for (int j = 0; j < 4; j++)
#pragma unroll
            for (int e = 0; e < 4; e++) S[i][j][e] = 0.0f;

    // QK
#pragma unroll
    for (int kk = 0; kk < 4; kk++) {
        uint32_t af[2][4], bf[4][2];
#pragma unroll
        for (int tm = 0; tm < 2; tm++)
            ldsm4(af[tm], qSb + aoffQ + tm * 16 * QSTRIDE * 2 + kk * 32);
#pragma unroll
        for (int tnp = 0; tnp < 2; tnp++) {
            uint32_t bb[4];
            ldsm4(bb, kSb + boffQ + tnp * 16 * QSTRIDE * 2 + kk * 32);
            bf[2*tnp][0] = bb[0]; bf[2*tnp][1] = bb[1];
            bf[2*tnp+1][0] = bb[2]; bf[2*tnp+1][1] = bb[3];
        }
#pragma unroll
        for (int tm = 0; tm < 2; tm++)
#pragma unroll
            for (int tn = 0; tn < 4; tn++) mma16(S[tm][tn], af[tm], bf[tn]);
    }

    for (int pass = 0; pass < 2; pass++) {
        if (pass == 1) {
            const float* bp = g_pq + (size_t)(dmin + brow) * HID + h * DHEAD + bdh;
            uint32_t ub[16];
#pragma unroll
            for (int f = 0; f < 8; f++) {
                float4 a = *(const float4*)(bp + f * 4);
                ub[f*2] = f2bf2(a.x, a.y); ub[f*2+1] = f2bf2(a.z, a.w);
            }
            uint32_t* db = (uint32_t*)&bS[brow * QSTRIDE + bdh];
#pragma unroll
            for (int f = 0; f < 4; f++)
                *(uint4*)(db + f * 4) = make_uint4(ub[f*4], ub[f*4+1], ub[f*4+2], ub[f*4+3]);
            __syncthreads();
        }
        const uint32_t Xb = (pass == 0) ? qSb : kSb;
        for (int bh = 0; bh < 2; bh++) {
            float Ga[2][4][4];
#pragma unroll
            for (int i = 0; i < 2; i++)
#pragma unroll
                for (int j = 0; j < 4; j++)
#pragma unroll
                    for (int e = 0; e < 4; e++) Ga[i][j][e] = 0.0f;
#pragma unroll
            for (int kk = 0; kk < 4; kk++) {
                uint32_t af[2][4], bf[4][2];
#pragma unroll
                for (int tm = 0; tm < 2; tm++)
                    ldsm4(af[tm], Xb + aoffQ + tm * 16 * QSTRIDE * 2 + kk * 32);
#pragma unroll
                for (int tnp = 0; tnp < 2; tnp++) {
                    uint32_t bb[4];
                    ldsm4(bb, bSb + boffQ + (bh * 128 + tnp * 16) * QSTRIDE * 2 + kk * 32);
                    bf[2*tnp][0] = bb[0]; bf[2*tnp][1] = bb[1];
                    bf[2*tnp+1][0] = bb[2]; bf[2*tnp+1][1] = bb[3];
                }
#pragma unroll
                for (int tm = 0; tm < 2; tm++)
#pragma unroll
                    for (int tn = 0; tn < 4; tn++) mma16(Ga[tm][tn], af[tm], bf[tn]);
            }
#pragma unroll
            for (int tm = 0; tm < 2; tm++)
#pragma unroll
                for (int tn = 0; tn < 4; tn++) {
                    const int r = wm * 32 + tm * 16 + g;
                    const int c = wn * 32 + tn * 8 + 2 * qd;
                    *(float2*)&Gs[r * 132 + c] = make_float2(Ga[tm][tn][0], Ga[tm][tn][1]);
                    *(float2*)&Gs[(r + 8) * 132 + c] = make_float2(Ga[tm][tn][2], Ga[tm][tn][3]);
                }
            __syncthreads();
#pragma unroll
            for (int tm = 0; tm < 2; tm++)
#pragma unroll
                for (int tn = 0; tn < 4; tn++) {
                    const int il = wm * 32 + tm * 16 + g;
                    const int jl = wn * 32 + tn * 8 + 2 * qd;
                    const int b0v = il - jl + 127 - bh * 128;
                    const int bv[4] = {b0v, b0v - 1, b0v + 8, b0v + 7};
                    int rv[4];
                    if (pass == 0) { rv[0] = il; rv[1] = il; rv[2] = il + 8; rv[3] = il + 8; }
                    else           { rv[0] = jl; rv[1] = jl + 1; rv[2] = jl; rv[3] = jl + 1; }
#pragma unroll
                    for (int e = 0; e < 4; e++)
                        if ((unsigned)bv[e] < 128u)
                            S[tm][tn][e] += Gs[rv[e] * 132 + bv[e]];
                }
            __syncthreads();
        }
    }

    // epilogue: exp -> bf16 store + partial row sums
    const float inv = 0.07216878364870322992f;
    float rs[2][2];
#pragma unroll
    for (int tm = 0; tm < 2; tm++) {
        float s0 = 0.0f, s1 = 0.0f;
        const int row = i0 + wm * 32 + tm * 16 + g;
        const int colb = j0 + wn * 32 + 2 * qd;
#pragma unroll
        for (int tn = 0; tn < 4; tn++) {
            float e0 = __expf(S[tm][tn][0] * inv);
            float e1 = __expf(S[tm][tn][1] * inv);
            float e2 = __expf(S[tm][tn][2] * inv);
            float e3 = __expf(S[tm][tn][3] * inv);
            s0 += e0 + e1; s1 += e2 + e3;
            *(uint32_t*)&g_scores[((size_t)h * NSEQ + row) * NSEQ + colb + tn * 8] = f2bf2(e0, e1);
            *(uint32_t*)&g_scores[((size_t)h * NSEQ + row + 8) * NSEQ + colb + tn * 8] = f2bf2(e2, e3);
        }
        rs[tm][0] = s0; rs[tm][1] = s1;
    }
#pragma unroll
    for (int tm = 0; tm < 2; tm++) {
        float s0 = rs[tm][0], s1 = rs[tm][1];
        s0 += __shfl_xor_sync(0xffffffffu, s0, 1);
        s0 += __shfl_xor_sync(0xffffffffu, s0, 2);
        s1 += __shfl_xor_sync(0xffffffffu, s1, 1);
        s1 += __shfl_xor_sync(0xffffffffu, s1, 2);
        if (qd == 0) {
            const int r = wm * 32 + tm * 16 + g;
            Gs[r * 4 + wn] = s0;
            Gs[(r + 8) * 4 + wn] = s1;
        }
    }
    __syncthreads();
    if (t < 128) {
        float tot = Gs[t * 4] + Gs[t * 4 + 1] + Gs[t * 4 + 2] + Gs[t * 4 + 3];
        g_psum[((size_t)(h << 10) + i0 + t) * 8 + blockIdx.x] = tot;
    }
}

// ============== rinv: 1/rowsum ==============
__global__ __launch_bounds__(256)
void rinv_kernel()
{
    const int i = blockIdx.x * 256 + threadIdx.x;
    const float* pp = g_psum + (size_t)i * 8;
    float4 a = *(const float4*)pp, b = *(const float4*)(pp + 4);
    g_rinv[i] = 1.0f / (a.x + a.y + a.z + a.w + b.x + b.y + b.z + b.w);
}

#define PSTRIDE 40

// ====== AV v3 (fixed): v1 structure, bf16 P loads (FULL 32-col staging) ======
__global__ __launch_bounds__(256)
void av_mma()
{
    __shared__ __nv_bfloat16 Ps[128 * PSTRIDE];
    __shared__ __nv_bfloat16 Vt[64 * PSTRIDE];
    const int h = blockIdx.y, i0 = blockIdx.x * 128;
    const int t = threadIdx.x, lane = t & 31, warp = t >> 5;
    const int g = lane >> 2, qd = lane & 3;
    const int wm = warp >> 2, wn = warp & 3;
    const int lr7 = lane & 7;

    const uint32_t aoffP = ((uint32_t)((wm * 64 + lr7 + ((lane >> 3) & 1) * 8) * PSTRIDE
                           + (lane >> 4) * 8)) * 2;
    const uint32_t boffV = ((uint32_t)((wn * 16 + lr7 + (lane >> 4) * 8) * PSTRIDE
                           + ((lane >> 3) & 1) * 8)) * 2;
    const uint32_t PsB = smem_u32(Ps), VtB = smem_u32(Vt);

    const int lrow = t >> 1, lj = (t & 1) * 16;
    const __nv_bfloat16* sp = g_scores + ((size_t)h * NSEQ + i0 + lrow) * NSEQ + lj;

    float rv[4][2];
#pragma unroll
    for (int tm = 0; tm < 4; tm++) {
        const int rl = wm * 64 + tm * 16 + g;
        rv[tm][0] = g_rinv[h * NSEQ + i0 + rl];
        rv[tm][1] = g_rinv[h * NSEQ + i0 + rl + 8];
    }

    float acc[4][2][4];
#pragma unroll
    for (int i = 0; i < 4; i++)
#pragma unroll
        for (int j = 0; j < 2; j++)
#pragma unroll
            for (int e = 0; e < 4; e++) acc[i][j][e] = 0.0f;

    for (int jt = 0; jt < NSEQ; jt += 32) {
        __syncthreads();
        // stage P: 16 bf16 per thread = full 32 cols per row (BUGFIX: 2 uint4s)
        {
            uint4 u0 = *(const uint4*)(sp + jt);
            uint4 u1 = *(const uint4*)(sp + jt + 8);
            *(uint4*)&Ps[lrow * PSTRIDE + lj] = u0;
            *(uint4*)&Ps[lrow * PSTRIDE + lj + 8] = u1;
        }
        // stage V transposed: Vt[d][j]
        {
            const int vr = t >> 3, dblk = (t & 7) * 8;
            const float* vp = g_v + (size_t)(jt + vr) * HID + h * DHEAD + dblk;
            float4 a = *(const float4*)vp;
            float4 b = *(const float4*)(vp + 4);
            Vt[(dblk + 0) * PSTRIDE + vr] = __float2bfloat16(a.x);
            Vt[(dblk + 1) * PSTRIDE + vr] = __float2bfloat16(a.y);
            Vt[(dblk + 2) * PSTRIDE + vr] = __float2bfloat16(a.z);
            Vt[(dblk + 3) * PSTRIDE + vr] = __float2bfloat16(a.w);
            Vt[(dblk + 4) * PSTRIDE + vr] = __float2bfloat16(b.x);
            Vt[(dblk + 5) * PSTRIDE + vr] = __float2bfloat16(b.y);
            Vt[(dblk + 6) * PSTRIDE + vr] = __float2bfloat16(b.z);
            Vt[(dblk + 7) * PSTRIDE + vr] = __float2bfloat16(b.w);
        }
        __syncthreads();
#pragma unroll
        for (int kk = 0; kk < 2; kk++) {
            uint32_t af[4][4], bf[2][2];
#pragma unroll
            for (int tm = 0; tm < 4; tm++)
                ldsm4(af[tm], PsB + aoffP + tm * 16 * PSTRIDE * 2 + kk * 32);
            {
                uint32_t bb[4];
                ldsm4(bb, VtB + boffV + kk * 32);
                bf[0][0] = bb[0]; bf[0][1] = bb[1];
                bf[1][0] = bb[2]; bf[1][1] = bb[3];
            }
#pragma unroll
            for (int tm = 0; tm < 4; tm++)
#pragma unroll
                for (int tn = 0; tn < 2; tn++) mma16(acc[tm][tn], af[tm], bf[tn]);
        }
    }
#pragma unroll
    for (int tm = 0; tm < 4; tm++)
#pragma unroll
        for (int tn = 0; tn < 2; tn++) {
            const int row = i0 + wm * 64 + tm * 16 + g;
            const int col = h * DHEAD + wn * 16 + tn * 8 + 2 * qd;
            *(float2*)&g_ctx[(size_t)row * HID + col] =
                make_float2(acc[tm][tn][0] * rv[tm][0], acc[tm][tn][1] * rv[tm][0]);
            *(float2*)&g_ctx[(size_t)(row + 8) * HID + col] =
                make_float2(acc[tm][tn][2] * rv[tm][1], acc[tm][tn][3] * rv[tm][1]);
        }
}

// ============== residual + LayerNorm =========================================
__global__ __launch_bounds__(256)
void ln_kernel(const float* __restrict__ hs, const float* __restrict__ gg,
               const float* __restrict__ bb, float* __restrict__ out)
{
    const int row = blockIdx.x, t = threadIdx.x;
    __shared__ float red[8];
    float4 p = *(const float4*)(g_proj + (size_t)row * HID + t * 4);
    float4 hv = *(const float4*)(hs + (size_t)row * HID + t * 4);
    float x0 = p.x+hv.x, x1 = p.y+hv.y, x2 = p.z+hv.z, x3 = p.w+hv.w;
    float s = x0+x1+x2+x3;
#pragma unroll
    for (int o = 16; o > 0; o >>= 1) s += __shfl_xor_sync(0xffffffffu, s, o);
    if ((t & 31) == 0) red[t >> 5] = s;
    __syncthreads();
    float mu = (red[0]+red[1]+red[2]+red[3]+red[4]+red[5]+red[6]+red[7]) * (1.0f/1024.0f);
    float d0 = x0-mu, d1 = x1-mu, d2 = x2-mu, d3 = x3-mu;
    float sq = d0*d0 + d1*d1 + d2*d2 + d3*d3;
#pragma unroll
    for (int o = 16; o > 0; o >>= 1) sq += __shfl_xor_sync(0xffffffffu, sq, o);
    __syncthreads();
    if ((t & 31) == 0) red[t >> 5] = sq;
    __syncthreads();
    float var = (red[0]+red[1]+red[2]+red[3]+red[4]+red[5]+red[6]+red[7]) * (1.0f/1024.0f);
    float rstd = rsqrtf(var + 1e-7f);
    float4 g4 = *(const float4*)(gg + t * 4);
    float4 b4 = *(const float4*)(bb + t * 4);
    *(float4*)(out + (size_t)row * HID + t * 4) =
        make_float4(d0*rstd*g4.x + b4.x, d1*rstd*g4.y + b4.y,
                    d2*rstd*g4.z + b4.z, d3*rstd*g4.w + b4.w);
}

extern "C" void kernel_launch(void* const* d_in, const int* in_sizes, int n_in,
                              void* d_out, int out_size)
{
    const float* hs  = (const float*)d_in[0];
    const float* rel = (const float*)d_in[1];
    const float* Wq  = (const float*)d_in[2];  const float* bq  = (const float*)d_in[3];
    const float* Wk  = (const float*)d_in[4];  const float* bk  = (const float*)d_in[5];
    const float* Wv  = (const float*)d_in[6];  const float* bv  = (const float*)d_in[7];
    const float* Wpk = (const float*)d_in[8];  const float* bpk = (const float*)d_in[9];
    const float* Wpq = (const float*)d_in[10]; const float* bpq = (const float*)d_in[11];
    const float* Wo  = (const float*)d_in[12]; const float* bo  = (const float*)d_in[13];
    const float* lng = (const float*)d_in[14]; const float* lnb = (const float*)d_in[15];

    float *q_, *k_, *v_, *pk_, *pq_, *ctx_, *proj_;
    cudaGetSymbolAddress((void**)&q_, g_q);
    cudaGetSymbolAddress((void**)&k_, g_k);
    cudaGetSymbolAddress((void**)&v_, g_v);
    cudaGetSymbolAddress((void**)&pk_, g_pk);
    cudaGetSymbolAddress((void**)&pq_, g_pq);
    cudaGetSymbolAddress((void**)&ctx_, g_ctx);
    cudaGetSymbolAddress((void**)&proj_, g_proj);

    const int score_smem = (2 * 128 * QSTRIDE + 256 * QSTRIDE) * 2 + 128 * 132 * 4;
    cudaFuncSetAttribute(score_mma, cudaFuncAttributeMaxDynamicSharedMemorySize, score_smem);

    gemm_bf16<<<dim3(8, 8, 3), 256>>>(hs, Wq, bq, q_, Wk, bk, k_, Wv, bv, v_);
    gemm_bf16<<<dim3(8, 16, 2), 256>>>(rel, Wpk, bpk, pk_, Wpq, bpq, pq_, Wpq, bpq, pq_);
    score_mma<<<dim3(8, 8, 16), 512, score_smem>>>();
    rinv_kernel<<<64, 256>>>();
    av_mma<<<dim3(8, 16), 256>>>();
    gemm_bf16<<<dim3(8, 8, 1), 256>>>(ctx_, Wo, bo, proj_, Wo, bo, proj_, Wo, bo, proj_);
    ln_kernel<<<1024, 256>>>(hs, lng, lnb, (float*)d_out);
}